// round 2
// baseline (speedup 1.0000x reference)
#include <cuda_runtime.h>
#include <stdint.h>

#define BATCH 128
#define N_RX 34
#define IMG_H 512
#define IMG_W 512
#define N_PIX (IMG_H * IMG_W)

// Block geometry: 512 threads, each writes 1 float4 per channel.
// Block covers 512*4 = 2048 pixels = 4 rows. 128 tiles per batch image.
#define THREADS 512
#define PIX_PER_BLOCK (THREADS * 4)   // 2048
#define ROWS_PER_BLOCK (PIX_PER_BLOCK / IMG_W)  // 4
#define TILES_PER_BATCH (N_PIX / PIX_PER_BLOCK) // 128

__global__ __launch_bounds__(THREADS)
void fused_vec2im_kernel(const float* __restrict__ x_vecs,
                         const float* __restrict__ dw,
                         const float* __restrict__ db,
                         const float* __restrict__ cw,
                         const float* __restrict__ cb,
                         float* __restrict__ out) {
    __shared__ int   s_y[N_RX];     // -1 = not in this block's rows
    __shared__ int   s_x[N_RX];
    __shared__ float s_p[N_RX];
    __shared__ float s_raw[N_RX];
    __shared__ int   s_cnt;

    const int tile = blockIdx.x;          // 0..127
    const int b    = blockIdx.y;          // 0..127
    const int tid  = threadIdx.x;

    const int pix0 = tile * PIX_PER_BLOCK;      // first pixel of this block
    const int y0   = pix0 / IMG_W;              // first row (tile*4)

    if (tid == 0) s_cnt = 0;
    __syncthreads();

    // ---- Phase A: load this batch's points, keep those in our row range ----
    if (tid < N_RX) {
        const float4 v = *reinterpret_cast<const float4*>(
            x_vecs + ((size_t)b * N_RX + tid) * 4);
        int yy = (int)rintf(v.z);   // col 2 -> y
        if (yy >= y0 && yy < y0 + ROWS_PER_BLOCK) {
            float raw  = v.x;
            float mask = (raw != 0.0f) ? 1.0f : 0.0f;
            float p    = raw * dw[tid] + mask * db[tid];
            int cat    = (int)v.w;
            p = p * cw[cat] + mask * cb[cat];
            s_y[tid]   = yy;
            s_x[tid]   = (int)rintf(v.y);  // col 1 -> x
            s_p[tid]   = p;
            s_raw[tid] = raw;
            atomicAdd(&s_cnt, 1);
        } else {
            s_y[tid] = -1;
        }
    }
    __syncthreads();

    // ---- Phase B: streaming write of this thread's 4 pixels, both channels ----
    const int pix = pix0 + tid * 4;       // 16B-aligned, coalesced across block
    float4 f0 = make_float4(0.f, 0.f, 0.f, 0.f);  // channel 0 (p)
    float4 f1 = make_float4(0.f, 0.f, 0.f, 0.f);  // channel 1 (raw)

    if (s_cnt != 0) {
        const int my_y = pix >> 9;        // pix / 512
        const int my_x = pix & (IMG_W - 1);
        // Ascending rx order => later rx overwrites => exact last-wins.
        #pragma unroll 2
        for (int rr = 0; rr < N_RX; rr++) {
            if (s_y[rr] == my_y) {
                int dx = s_x[rr] - my_x;
                if ((unsigned)dx < 4u) {
                    float p   = s_p[rr];
                    float raw = s_raw[rr];
                    if (dx == 0) { f0.x = p; f1.x = raw; }
                    else if (dx == 1) { f0.y = p; f1.y = raw; }
                    else if (dx == 2) { f0.z = p; f1.z = raw; }
                    else { f0.w = p; f1.w = raw; }
                }
            }
        }
    }

    float4* out4_c0 = reinterpret_cast<float4*>(
        out + (size_t)b * 2 * N_PIX) + (pix >> 2);
    float4* out4_c1 = reinterpret_cast<float4*>(
        out + (size_t)b * 2 * N_PIX + N_PIX) + (pix >> 2);
    *out4_c0 = f0;
    *out4_c1 = f1;
}

extern "C" void kernel_launch(void* const* d_in, const int* in_sizes, int n_in,
                              void* d_out, int out_size) {
    const float* x_vecs = (const float*)d_in[0];
    const float* dw     = (const float*)d_in[1];
    const float* db     = (const float*)d_in[2];
    const float* cw     = (const float*)d_in[3];
    const float* cb     = (const float*)d_in[4];
    float* out = (float*)d_out;

    dim3 grid(TILES_PER_BATCH, BATCH);   // (128, 128)
    fused_vec2im_kernel<<<grid, THREADS>>>(x_vecs, dw, db, cw, cb, out);
}